// round 6
// baseline (speedup 1.0000x reference)
#include <cuda_runtime.h>
#include <math.h>

#define BB 4
#define SS 1024
#define DD 1024
#define HH 16
#define DKK 64
#define DFFV 4096
#define MR (BB*SS)
#define LN_EPS 1e-6f

__device__ float g_xn [MR*DD];
__device__ float g_q  [MR*DD];
__device__ float g_k  [MR*DD];
__device__ float g_v  [MR*DD];
__device__ float g_ctx[MR*DD];
__device__ float g_x1 [MR*DD];
__device__ float g_xn2[MR*DD];
__device__ float g_ffh[MR*DFFV];

__device__ __forceinline__ float tf32r(float x) {
    unsigned u;
    asm("cvt.rna.tf32.f32 %0, %1;" : "=r"(u) : "f"(x));
    return __uint_as_float(u);
}

__device__ __forceinline__ void mma_tf32(float* c, const float* a, float b0f, float b1f) {
    asm volatile(
        "mma.sync.aligned.m16n8k8.row.col.f32.tf32.tf32.f32 "
        "{%0,%1,%2,%3}, {%4,%5,%6,%7}, {%8,%9}, {%0,%1,%2,%3};\n"
        : "+f"(c[0]), "+f"(c[1]), "+f"(c[2]), "+f"(c[3])
        : "r"(__float_as_uint(a[0])), "r"(__float_as_uint(a[1])),
          "r"(__float_as_uint(a[2])), "r"(__float_as_uint(a[3])),
          "r"(__float_as_uint(b0f)), "r"(__float_as_uint(b1f)));
}

__device__ __forceinline__ void mma_tf32u(float* c, const unsigned* a, unsigned b0, unsigned b1) {
    asm volatile(
        "mma.sync.aligned.m16n8k8.row.col.f32.tf32.tf32.f32 "
        "{%0,%1,%2,%3}, {%4,%5,%6,%7}, {%8,%9}, {%0,%1,%2,%3};\n"
        : "+f"(c[0]), "+f"(c[1]), "+f"(c[2]), "+f"(c[3])
        : "r"(a[0]), "r"(a[1]), "r"(a[2]), "r"(a[3]), "r"(b0), "r"(b1));
}

// LayerNorm: torch ddof=1, eps on std; output tf32-rounded
__global__ __launch_bounds__(256)
void layernorm_kernel(const float* __restrict__ x, float* __restrict__ out,
                      const float* __restrict__ alpha, const float* __restrict__ beta)
{
    int row = blockIdx.x;
    float4 v = ((const float4*)(x + (long)row * DD))[threadIdx.x];
    float s  = v.x + v.y + v.z + v.w;
    float sq = v.x*v.x + v.y*v.y + v.z*v.z + v.w*v.w;
    #pragma unroll
    for (int o = 16; o; o >>= 1) {
        s  += __shfl_down_sync(0xffffffffu, s,  o);
        sq += __shfl_down_sync(0xffffffffu, sq, o);
    }
    __shared__ float red[16];
    __shared__ float stats[2];
    int warp = threadIdx.x >> 5, lane = threadIdx.x & 31;
    if (lane == 0) { red[warp] = s; red[warp + 8] = sq; }
    __syncthreads();
    if (threadIdx.x == 0) {
        float ts = 0.f, tq = 0.f;
        #pragma unroll
        for (int i = 0; i < 8; i++) { ts += red[i]; tq += red[i + 8]; }
        float mean = ts / (float)DD;
        float var  = (tq - (float)DD * mean * mean) / (float)(DD - 1);
        var = fmaxf(var, 0.f);
        stats[0] = mean; stats[1] = 1.f / (sqrtf(var) + LN_EPS);
    }
    __syncthreads();
    float mean = stats[0], rstd = stats[1];
    float a = alpha[0], b = beta[0];
    float4 o;
    o.x = tf32r(a * (v.x - mean) * rstd + b);
    o.y = tf32r(a * (v.y - mean) * rstd + b);
    o.z = tf32r(a * (v.z - mean) * rstd + b);
    o.w = tf32r(a * (v.w - mean) * rstd + b);
    ((float4*)(out + (long)row * DD))[threadIdx.x] = o;
}

// tf32 tensor-core GEMM: 128x128 tile, BK=16, 8 warps (2x4), warp 64x32
#define AST 20
#define BST 132

__device__ __forceinline__ float4 cvt4(float4 v) {
    v.x = tf32r(v.x); v.y = tf32r(v.y); v.z = tf32r(v.z); v.w = tf32r(v.w);
    return v;
}

template<bool BIAS, bool RELU, bool RES, bool CVT>
__global__ __launch_bounds__(256)
void mma_gemm(const float* __restrict__ A, const float* __restrict__ Bm,
              const float* __restrict__ bias, const float* __restrict__ res,
              float* __restrict__ C, int K, int N)
{
    __shared__ float As[2][128 * AST];
    __shared__ float Bs[2][16 * BST];

    int tid = threadIdx.x;
    int rowBase = blockIdx.y << 7, colBase = blockIdx.x << 7;
    const float* Ag = A + (long)rowBase * K;
    const float* Bg = Bm + colBase;

    int a_r = tid >> 2, a_c = (tid & 3) << 2;
    int b_k = tid >> 5, b_c = (tid & 31) << 2;
    int warp = tid >> 5, lane = tid & 31;
    int lq = lane >> 2, lr = lane & 3;
    int wm = warp >> 2, wn = warp & 3;

    float acc[4][4][4];
    #pragma unroll
    for (int i = 0; i < 4; i++)
        #pragma unroll
        for (int j = 0; j < 4; j++)
            #pragma unroll
            for (int v = 0; v < 4; v++) acc[i][j][v] = 0.f;

    int T = K >> 4;
    float4 va0 = *(const float4*)(Ag + a_r * K + a_c);
    float4 va1 = *(const float4*)(Ag + (a_r + 64) * K + a_c);
    float4 vb0 = cvt4(*(const float4*)(Bg + (long)b_k * N + b_c));
    float4 vb1 = cvt4(*(const float4*)(Bg + (long)(b_k + 8) * N + b_c));
    *(float4*)&As[0][a_r * AST + a_c]        = va0;
    *(float4*)&As[0][(a_r + 64) * AST + a_c] = va1;
    *(float4*)&Bs[0][b_k * BST + b_c]        = vb0;
    *(float4*)&Bs[0][(b_k + 8) * BST + b_c]  = vb1;

    for (int t = 0; t < T; t++) {
        __syncthreads();
        int buf = t & 1;
        if (t + 1 < T) {
            int k0 = (t + 1) << 4;
            va0 = *(const float4*)(Ag + a_r * K + k0 + a_c);
            va1 = *(const float4*)(Ag + (a_r + 64) * K + k0 + a_c);
            vb0 = cvt4(*(const float4*)(Bg + (long)(k0 + b_k) * N + b_c));
            vb1 = cvt4(*(const float4*)(Bg + (long)(k0 + b_k + 8) * N + b_c));
        }
        const float* Ab = As[buf];
        const float* Bb = Bs[buf];

        unsigned a[4][2][4], b[4][2][2];
        #pragma unroll
        for (int mt = 0; mt < 4; mt++) {
            int r0 = (wm * 64 + mt * 16 + lq) * AST + lr;
            #pragma unroll
            for (int ks = 0; ks < 2; ks++) {
                a[mt][ks][0] = *(const unsigned*)&Ab[r0 + ks * 8];
                a[mt][ks][1] = *(const unsigned*)&Ab[r0 + 8 * AST + ks * 8];
                a[mt][ks][2] = *(const unsigned*)&Ab[r0 + ks * 8 + 4];
                a[mt][ks][3] = *(const unsigned*)&Ab[r0 + 8 * AST + ks * 8 + 4];
            }
        }
        #pragma unroll
        for (int nt = 0; nt < 4; nt++) {
            int c0 = wn * 32 + nt * 8 + lq;
            #pragma unroll
            for (int ks = 0; ks < 2; ks++) {
                b[nt][ks][0] = *(const unsigned*)&Bb[(ks * 8 + lr) * BST + c0];
                b[nt][ks][1] = *(const unsigned*)&Bb[(ks * 8 + lr + 4) * BST + c0];
            }
        }
        #pragma unroll
        for (int ks = 0; ks < 2; ks++)
            #pragma unroll
            for (int mt = 0; mt < 4; mt++)
                #pragma unroll
                for (int nt = 0; nt < 4; nt++)
                    mma_tf32u(acc[mt][nt], a[mt][ks], b[nt][ks][0], b[nt][ks][1]);

        if (t + 1 < T) {
            *(float4*)&As[buf ^ 1][a_r * AST + a_c]        = va0;
            *(float4*)&As[buf ^ 1][(a_r + 64) * AST + a_c] = va1;
            *(float4*)&Bs[buf ^ 1][b_k * BST + b_c]        = vb0;
            *(float4*)&Bs[buf ^ 1][(b_k + 8) * BST + b_c]  = vb1;
        }
    }

    int erow = rowBase + wm * 64 + lq;
    int ecol = colBase + wn * 32 + lr * 2;
    #pragma unroll
    for (int mt = 0; mt < 4; mt++) {
        #pragma unroll
        for (int nt = 0; nt < 4; nt++) {
            int r = erow + mt * 16;
            int c = ecol + nt * 8;
            float lo0 = acc[mt][nt][0], lo1 = acc[mt][nt][1];
            float hi0 = acc[mt][nt][2], hi1 = acc[mt][nt][3];
            if (BIAS) {
                float2 bv = *(const float2*)(bias + c);
                lo0 += bv.x; lo1 += bv.y; hi0 += bv.x; hi1 += bv.y;
            }
            if (RELU) {
                lo0 = fmaxf(lo0, 0.f); lo1 = fmaxf(lo1, 0.f);
                hi0 = fmaxf(hi0, 0.f); hi1 = fmaxf(hi1, 0.f);
            }
            if (RES) {
                float2 r0 = *(const float2*)(res + (long)r * N + c);
                float2 r1 = *(const float2*)(res + (long)(r + 8) * N + c);
                lo0 += r0.x; lo1 += r0.y; hi0 += r1.x; hi1 += r1.y;
            }
            if (CVT) {
                lo0 = tf32r(lo0); lo1 = tf32r(lo1);
                hi0 = tf32r(hi0); hi1 = tf32r(hi1);
            }
            float2 wlo = {lo0, lo1}, whi = {hi0, hi1};
            *(float2*)(C + (long)r * N + c)       = wlo;
            *(float2*)(C + (long)(r + 8) * N + c) = whi;
        }
    }
}

// ---------------- tensor-core flash attention ----------------
// CTA: 8 warps x 16 q rows = 128 q rows; k-tiles of 64.
// Q frags in regs; K smem stride-68; V smem xor-8 swizzle; P via quad shuffles.
#define KST 68

__global__ __launch_bounds__(256)
void attention_mma(const float* __restrict__ q, const float* __restrict__ k,
                   const float* __restrict__ v, const int* __restrict__ mask,
                   float* __restrict__ ctx)
{
    __shared__ float Ks[64 * KST];
    __shared__ float Vs[64 * 64];
    __shared__ int   msk[64];

    int tid = threadIdx.x;
    int w = tid >> 5, lane = tid & 31;
    int lq = lane >> 2, lr = lane & 3;
    int bh = blockIdx.y;
    int b = bh >> 4, h = bh & 15;
    int q0 = blockIdx.x * 128;

    const float* qg = q + ((long)(b * SS + q0 + w * 16)) * DD + h * DKK;
    const float* kg = k + ((long)b * SS) * DD + h * DKK;
    const float* vg = v + ((long)b * SS) * DD + h * DKK;
    const int* mrow = mask + b * SS;

    // Q fragments (a-layout), resident for whole kernel. Already tf32 (CVT proj).
    float qa[8][4];
    #pragma unroll
    for (int ks = 0; ks < 8; ks++) {
        qa[ks][0] = qg[(long)lq * DD + ks * 8 + lr];
        qa[ks][1] = qg[(long)(lq + 8) * DD + ks * 8 + lr];
        qa[ks][2] = qg[(long)lq * DD + ks * 8 + lr + 4];
        qa[ks][3] = qg[(long)(lq + 8) * DD + ks * 8 + lr + 4];
    }

    float m0 = -INFINITY, m1 = -INFINITY, l0 = 0.f, l1 = 0.f;
    float oacc[8][4];
    #pragma unroll
    for (int nt = 0; nt < 8; nt++)
        #pragma unroll
        for (int e = 0; e < 4; e++) oacc[nt][e] = 0.f;

    for (int kt = 0; kt < 16; kt++) {
        int k0 = kt * 64;
        __syncthreads();
        #pragma unroll
        for (int i = 0; i < 4; i++) {
            int fi = tid + i * 256;
            int kr = fi >> 4;
            int c4 = (fi & 15) << 2;
            float4 tk = *(const float4*)(kg + (long)(k0 + kr) * DD + c4);
            *(float4*)&Ks[kr * KST + c4] = tk;
            float4 tv = *(const float4*)(vg + (long)(k0 + kr) * DD + c4);
            *(float4*)&Vs[kr * 64 + (c4 ^ ((kr & 3) << 3))] = tv;
        }
        if (tid < 16) ((int4*)msk)[tid] = ((const int4*)(mrow + k0))[tid];
        __syncthreads();

        // S = Q K^T  (per warp: 16 x 64)
        float sacc[8][4];
        #pragma unroll
        for (int nt = 0; nt < 8; nt++)
            #pragma unroll
            for (int e = 0; e < 4; e++) sacc[nt][e] = 0.f;

        #pragma unroll
        for (int nt = 0; nt < 8; nt++) {
            int rb = (nt * 8 + lq) * KST;
            #pragma unroll
            for (int ks = 0; ks < 8; ks++) {
                float b0 = Ks[rb + ks * 8 + lr];
                float b1 = Ks[rb + ks * 8 + lr + 4];
                mma_tf32(sacc[nt], qa[ks], b0, b1);
            }
        }

        // mask + online softmax (rows lq -> c0,c1 ; lq+8 -> c2,c3)
        float rmax0 = -INFINITY, rmax1 = -INFINITY;
        #pragma unroll
        for (int nt = 0; nt < 8; nt++) {
            int c = nt * 8 + lr * 2;
            int mk0 = msk[c], mk1 = msk[c + 1];
            float s0 = sacc[nt][0] * 0.125f; if (mk0 == 0) s0 = -1e9f;
            float s1 = sacc[nt][1] * 0.125f; if (mk1 == 0) s1 = -1e9f;
            float s2 = sacc[nt][2] * 0.125f; if (mk0 == 0) s2 = -1e9f;
            float s3 = sacc[nt][3] * 0.125f; if (mk1 == 0) s3 = -1e9f;
            sacc[nt][0] = s0; sacc[nt][1] = s1; sacc[nt][2] = s2; sacc[nt][3] = s3;
            rmax0 = fmaxf(rmax0, fmaxf(s0, s1));
            rmax1 = fmaxf(rmax1, fmaxf(s2, s3));
        }
        rmax0 = fmaxf(rmax0, __shfl_xor_sync(0xffffffffu, rmax0, 1));
        rmax0 = fmaxf(rmax0, __shfl_xor_sync(0xffffffffu, rmax0, 2));
        rmax1 = fmaxf(rmax1, __shfl_xor_sync(0xffffffffu, rmax1, 1));
        rmax1 = fmaxf(rmax1, __shfl_xor_sync(0xffffffffu, rmax1, 2));
        float mn0 = fmaxf(m0, rmax0), mn1 = fmaxf(m1, rmax1);
        float corr0 = __expf(m0 - mn0), corr1 = __expf(m1 - mn1);
        float ps0 = 0.f, ps1 = 0.f;
        #pragma unroll
        for (int nt = 0; nt < 8; nt++) {
            float p0 = __expf(sacc[nt][0] - mn0);
            float p1 = __expf(sacc[nt][1] - mn0);
            float p2 = __expf(sacc[nt][2] - mn1);
            float p3 = __expf(sacc[nt][3] - mn1);
            ps0 += p0 + p1; ps1 += p2 + p3;
            sacc[nt][0] = p0; sacc[nt][1] = p1; sacc[nt][2] = p2; sacc[nt][3] = p3;
        }
        ps0 += __shfl_xor_sync(0xffffffffu, ps0, 1);
        ps0 += __shfl_xor_sync(0xffffffffu, ps0, 2);
        ps1 += __shfl_xor_sync(0xffffffffu, ps1, 1);
        ps1 += __shfl_xor_sync(0xffffffffu, ps1, 2);
        l0 = l0 * corr0 + ps0; m0 = mn0;
        l1 = l1 * corr1 + ps1; m1 = mn1;
        #pragma unroll
        for (int nt = 0; nt < 8; nt++) {
            oacc[nt][0] *= corr0; oacc[nt][1] *= corr0;
            oacc[nt][2] *= corr1; oacc[nt][3] *= corr1;
        }

        // O += P V : convert C frags of S-tile ks into A frags via quad shuffles
        int base = lane & ~3;
        int src0 = base | (lr >> 1);
        int src1 = src0 | 2;
        int sel = lr & 1;
        #pragma unroll
        for (int ks = 0; ks < 8; ks++) {
            float v0 = __shfl_sync(0xffffffffu, sacc[ks][0], src0);
            float v1 = __shfl_sync(0xffffffffu, sacc[ks][1], src0);
            float v2 = __shfl_sync(0xffffffffu, sacc[ks][2], src0);
            float v3 = __shfl_sync(0xffffffffu, sacc[ks][3], src0);
            float w0 = __shfl_sync(0xffffffffu, sacc[ks][0], src1);
            float w1 = __shfl_sync(0xffffffffu, sacc[ks][1], src1);
            float w2 = __shfl_sync(0xffffffffu, sacc[ks][2], src1);
            float w3 = __shfl_sync(0xffffffffu, sacc[ks][3], src1);
            float pa[4];
            pa[0] = tf32r(sel ? v1 : v0);
            pa[1] = tf32r(sel ? v3 : v2);
            pa[2] = tf32r(sel ? w1 : w0);
            pa[3] = tf32r(sel ? w3 : w2);
            int r0 = (ks * 8 + lr) * 64;
            int r1 = (ks * 8 + lr + 4) * 64;
            int xo = lr << 3;
            #pragma unroll
            for (int nt = 0; nt < 8; nt++) {
                int sw = (nt * 8 + lq) ^ xo;
                float b0 = Vs[r0 + sw];
                float b1 = Vs[r1 + sw];
                mma_tf32(oacc[nt], pa, b0, b1);
            }
        }
    }

    float inv0 = 1.f / l0, inv1 = 1.f / l1;
    long row0 = (long)(b * SS + q0 + w * 16 + lq) * DD + h * DKK;
    long row1 = row0 + 8 * DD;
    #pragma unroll
    for (int nt = 0; nt < 8; nt++) {
        int c = nt * 8 + lr * 2;
        float2 o0, o1;
        o0.x = tf32r(oacc[nt][0] * inv0); o0.y = tf32r(oacc[nt][1] * inv0);
        o1.x = tf32r(oacc[nt][2] * inv1); o1.y = tf32r(oacc[nt][3] * inv1);
        *(float2*)(ctx + row0 + c) = o0;
        *(float2*)(ctx + row1 + c) = o1;
    }
}

extern "C" void kernel_launch(void* const* d_in, const int* in_sizes, int n_in,
                              void* d_out, int out_size)
{
    const float* x    = (const float*)d_in[0];
    const int*   mask = (const int*)  d_in[1];
    const float* wq = (const float*)d_in[2];  const float* bq = (const float*)d_in[3];
    const float* wk = (const float*)d_in[4];  const float* bk = (const float*)d_in[5];
    const float* wv = (const float*)d_in[6];  const float* bv = (const float*)d_in[7];
    const float* wo = (const float*)d_in[8];  const float* bo = (const float*)d_in[9];
    const float* w1 = (const float*)d_in[10]; const float* b1 = (const float*)d_in[11];
    const float* w2 = (const float*)d_in[12]; const float* b2 = (const float*)d_in[13];
    const float* a1 = (const float*)d_in[14]; const float* be1 = (const float*)d_in[15];
    const float* a2 = (const float*)d_in[16]; const float* be2 = (const float*)d_in[17];
    float* out = (float*)d_out;

    float *xn, *q, *k, *v, *ctx, *x1, *xn2, *ffh;
    cudaGetSymbolAddress((void**)&xn,  g_xn);
    cudaGetSymbolAddress((void**)&q,   g_q);
    cudaGetSymbolAddress((void**)&k,   g_k);
    cudaGetSymbolAddress((void**)&v,   g_v);
    cudaGetSymbolAddress((void**)&ctx, g_ctx);
    cudaGetSymbolAddress((void**)&x1,  g_x1);
    cudaGetSymbolAddress((void**)&xn2, g_xn2);
    cudaGetSymbolAddress((void**)&ffh, g_ffh);

    dim3 gD (DD   / 128, MR / 128);
    dim3 gFF(DFFV / 128, MR / 128);

    layernorm_kernel<<<MR, 256>>>(x, xn, a1, be1);
    mma_gemm<true,  false, false, true ><<<gD, 256>>>(xn, wq, bq, nullptr, q, DD, DD);
    mma_gemm<true,  false, false, true ><<<gD, 256>>>(xn, wk, bk, nullptr, k, DD, DD);
    mma_gemm<true,  false, false, true ><<<gD, 256>>>(xn, wv, bv, nullptr, v, DD, DD);
    attention_mma<<<dim3(SS / 128, BB * HH), 256>>>(q, k, v, mask, ctx);
    mma_gemm<true,  false, true,  false><<<gD, 256>>>(ctx, wo, bo, x, x1, DD, DD);
    layernorm_kernel<<<MR, 256>>>(x1, xn2, a2, be2);
    mma_gemm<true,  true,  false, true ><<<gFF, 256>>>(xn2, w1, b1, nullptr, ffh, DD, DFFV);
    mma_gemm<true,  false, true,  false><<<gD, 256>>>(ffh, w2, b2, x1, out, DFFV, DD);
}

// round 8
// speedup vs baseline: 1.2313x; 1.2313x over previous
#include <cuda_runtime.h>
#include <math.h>

#define BB 4
#define SS 1024
#define DD 1024
#define HH 16
#define DKK 64
#define DFFV 4096
#define MR (BB*SS)
#define LN_EPS 1e-6f

__device__ float g_xn [MR*DD];
__device__ float g_q  [MR*DD];
__device__ float g_k  [MR*DD];
__device__ float g_v  [MR*DD];
__device__ float g_ctx[MR*DD];
__device__ float g_x1 [MR*DD];
__device__ float g_xn2[MR*DD];
__device__ float g_ffh[MR*DFFV];
__device__ float g_wq [DD*DD];
__device__ float g_wk [DD*DD];
__device__ float g_wv [DD*DD];
__device__ float g_wo [DD*DD];
__device__ float g_w1 [DD*DFFV];
__device__ float g_w2 [DFFV*DD];

__device__ __forceinline__ float tf32r(float x) {
    unsigned u;
    asm("cvt.rna.tf32.f32 %0, %1;" : "=r"(u) : "f"(x));
    return __uint_as_float(u);
}

__device__ __forceinline__ void mma_tf32(float* c, const float* a, float b0f, float b1f) {
    asm volatile(
        "mma.sync.aligned.m16n8k8.row.col.f32.tf32.tf32.f32 "
        "{%0,%1,%2,%3}, {%4,%5,%6,%7}, {%8,%9}, {%0,%1,%2,%3};\n"
        : "+f"(c[0]), "+f"(c[1]), "+f"(c[2]), "+f"(c[3])
        : "r"(__float_as_uint(a[0])), "r"(__float_as_uint(a[1])),
          "r"(__float_as_uint(a[2])), "r"(__float_as_uint(a[3])),
          "r"(__float_as_uint(b0f)), "r"(__float_as_uint(b1f)));
}

__device__ __forceinline__ void mma_tf32u(float* c, const unsigned* a, unsigned b0, unsigned b1) {
    asm volatile(
        "mma.sync.aligned.m16n8k8.row.col.f32.tf32.tf32.f32 "
        "{%0,%1,%2,%3}, {%4,%5,%6,%7}, {%8,%9}, {%0,%1,%2,%3};\n"
        : "+f"(c[0]), "+f"(c[1]), "+f"(c[2]), "+f"(c[3])
        : "r"(a[0]), "r"(a[1]), "r"(a[2]), "r"(a[3]), "r"(b0), "r"(b1));
}

__device__ __forceinline__ void cpasync16(unsigned saddr, const float* g) {
    asm volatile("cp.async.ca.shared.global [%0], [%1], 16;\n" :: "r"(saddr), "l"(g));
}
__device__ __forceinline__ void cpasync_commit() {
    asm volatile("cp.async.commit_group;\n" ::: "memory");
}
__device__ __forceinline__ void cpasync_wait0() {
    asm volatile("cp.async.wait_group 0;\n" ::: "memory");
}

__global__ __launch_bounds__(256)
void tf32_round_kernel(const float* __restrict__ in, float* __restrict__ out, int n4)
{
    int i = blockIdx.x * 256 + threadIdx.x;
    if (i < n4) {
        float4 v = ((const float4*)in)[i];
        v.x = tf32r(v.x); v.y = tf32r(v.y); v.z = tf32r(v.z); v.w = tf32r(v.w);
        ((float4*)out)[i] = v;
    }
}

// LayerNorm: torch ddof=1, eps on std; output tf32-rounded
__global__ __launch_bounds__(256)
void layernorm_kernel(const float* __restrict__ x, float* __restrict__ out,
                      const float* __restrict__ alpha, const float* __restrict__ beta)
{
    int row = blockIdx.x;
    float4 v = ((const float4*)(x + (long)row * DD))[threadIdx.x];
    float s  = v.x + v.y + v.z + v.w;
    float sq = v.x*v.x + v.y*v.y + v.z*v.z + v.w*v.w;
    #pragma unroll
    for (int o = 16; o; o >>= 1) {
        s  += __shfl_down_sync(0xffffffffu, s,  o);
        sq += __shfl_down_sync(0xffffffffu, sq, o);
    }
    __shared__ float red[16];
    __shared__ float stats[2];
    int warp = threadIdx.x >> 5, lane = threadIdx.x & 31;
    if (lane == 0) { red[warp] = s; red[warp + 8] = sq; }
    __syncthreads();
    if (threadIdx.x == 0) {
        float ts = 0.f, tq = 0.f;
        #pragma unroll
        for (int i = 0; i < 8; i++) { ts += red[i]; tq += red[i + 8]; }
        float mean = ts / (float)DD;
        float var  = (tq - (float)DD * mean * mean) / (float)(DD - 1);
        var = fmaxf(var, 0.f);
        stats[0] = mean; stats[1] = 1.f / (sqrtf(var) + LN_EPS);
    }
    __syncthreads();
    float mean = stats[0], rstd = stats[1];
    float a = alpha[0], b = beta[0];
    float4 o;
    o.x = tf32r(a * (v.x - mean) * rstd + b);
    o.y = tf32r(a * (v.y - mean) * rstd + b);
    o.z = tf32r(a * (v.z - mean) * rstd + b);
    o.w = tf32r(a * (v.w - mean) * rstd + b);
    ((float4*)(out + (long)row * DD))[threadIdx.x] = o;
}

// ---------------- tf32 GEMM: 128x128 CTA, 4 warps (2x2), warp 64x64, BK=16 ---
// cp.async double-buffer; both A and B are pre-rounded tf32.
#define AST 20
#define BST 136

template<bool BIAS, bool RELU, bool RES, bool CVT>
__global__ __launch_bounds__(128, 2)
void mma_gemm(const float* __restrict__ A, const float* __restrict__ Bm,
              const float* __restrict__ bias, const float* __restrict__ res,
              float* __restrict__ C, int K, int N)
{
    __shared__ float As[2][128 * AST];
    __shared__ float Bs[2][16 * BST];

    int tid = threadIdx.x;
    int warp = tid >> 5, lane = tid & 31;
    int lq = lane >> 2, lr = lane & 3;
    int wm = warp >> 1, wn = warp & 1;
    int rowBase = blockIdx.y << 7, colBase = blockIdx.x << 7;

    // loader mapping: A -> thread = one row (16 k); B -> 4 k-rows x 16 cols
    int a_row = tid;
    int b_row = tid >> 3;
    int b_col = (tid & 7) << 4;

    const float* Agp = A + (long)(rowBase + a_row) * K;
    const float* Bgp = Bm + (long)b_row * N + colBase + b_col;

    unsigned aB[2], bB[2];
    aB[0] = (unsigned)__cvta_generic_to_shared(&As[0][a_row * AST]);
    aB[1] = (unsigned)__cvta_generic_to_shared(&As[1][a_row * AST]);
    bB[0] = (unsigned)__cvta_generic_to_shared(&Bs[0][b_row * BST + b_col]);
    bB[1] = (unsigned)__cvta_generic_to_shared(&Bs[1][b_row * BST + b_col]);

    float acc[4][8][4];
    #pragma unroll
    for (int i = 0; i < 4; i++)
        #pragma unroll
        for (int j = 0; j < 8; j++)
            #pragma unroll
            for (int e = 0; e < 4; e++) acc[i][j][e] = 0.f;

    int T = K >> 4;
    // prologue: fill buffer 0
    #pragma unroll
    for (int i = 0; i < 4; i++) cpasync16(aB[0] + i * 16, Agp + i * 4);
    #pragma unroll
    for (int i = 0; i < 4; i++) cpasync16(bB[0] + i * 16, Bgp + i * 4);
    cpasync_commit();

    for (int t = 0; t < T; t++) {
        cpasync_wait0();
        __syncthreads();
        int buf = t & 1;
        if (t + 1 < T) {
            int k0 = (t + 1) << 4;
            #pragma unroll
            for (int i = 0; i < 4; i++) cpasync16(aB[buf ^ 1] + i * 16, Agp + k0 + i * 4);
            #pragma unroll
            for (int i = 0; i < 4; i++) cpasync16(bB[buf ^ 1] + i * 16, Bgp + (long)k0 * N + i * 4);
            cpasync_commit();
        }
        const float* Ab = As[buf];
        const float* Bb = Bs[buf];

        unsigned a[4][2][4], b[8][2][2];
        #pragma unroll
        for (int mt = 0; mt < 4; mt++) {
            int r0 = (wm * 64 + mt * 16 + lq) * AST + lr;
            #pragma unroll
            for (int ks = 0; ks < 2; ks++) {
                a[mt][ks][0] = *(const unsigned*)&Ab[r0 + ks * 8];
                a[mt][ks][1] = *(const unsigned*)&Ab[r0 + 8 * AST + ks * 8];
                a[mt][ks][2] = *(const unsigned*)&Ab[r0 + ks * 8 + 4];
                a[mt][ks][3] = *(const unsigned*)&Ab[r0 + 8 * AST + ks * 8 + 4];
            }
        }
        #pragma unroll
        for (int nt = 0; nt < 8; nt++) {
            int c0 = wn * 64 + nt * 8 + lq;
            #pragma unroll
            for (int ks = 0; ks < 2; ks++) {
                b[nt][ks][0] = *(const unsigned*)&Bb[(ks * 8 + lr) * BST + c0];
                b[nt][ks][1] = *(const unsigned*)&Bb[(ks * 8 + lr + 4) * BST + c0];
            }
        }
        #pragma unroll
        for (int ks = 0; ks < 2; ks++)
            #pragma unroll
            for (int mt = 0; mt < 4; mt++)
                #pragma unroll
                for (int nt = 0; nt < 8; nt++)
                    mma_tf32u(acc[mt][nt], a[mt][ks], b[nt][ks][0], b[nt][ks][1]);
    }

    int erow = rowBase + wm * 64 + lq;
    int ecol = colBase + wn * 64 + lr * 2;
    #pragma unroll
    for (int mt = 0; mt < 4; mt++) {
        #pragma unroll
        for (int nt = 0; nt < 8; nt++) {
            int r = erow + mt * 16;
            int c = ecol + nt * 8;
            float lo0 = acc[mt][nt][0], lo1 = acc[mt][nt][1];
            float hi0 = acc[mt][nt][2], hi1 = acc[mt][nt][3];
            if (BIAS) {
                float2 bv = *(const float2*)(bias + c);
                lo0 += bv.x; lo1 += bv.y; hi0 += bv.x; hi1 += bv.y;
            }
            if (RELU) {
                lo0 = fmaxf(lo0, 0.f); lo1 = fmaxf(lo1, 0.f);
                hi0 = fmaxf(hi0, 0.f); hi1 = fmaxf(hi1, 0.f);
            }
            if (RES) {
                float2 r0 = *(const float2*)(res + (long)r * N + c);
                float2 r1 = *(const float2*)(res + (long)(r + 8) * N + c);
                lo0 += r0.x; lo1 += r0.y; hi0 += r1.x; hi1 += r1.y;
            }
            if (CVT) {
                lo0 = tf32r(lo0); lo1 = tf32r(lo1);
                hi0 = tf32r(hi0); hi1 = tf32r(hi1);
            }
            float2 wlo = {lo0, lo1}, whi = {hi0, hi1};
            *(float2*)(C + (long)r * N + c)       = wlo;
            *(float2*)(C + (long)(r + 8) * N + c) = whi;
        }
    }
}

// ---------------- tensor-core flash attention (unchanged from R6) ------------
#define KST 68

__global__ __launch_bounds__(256)
void attention_mma(const float* __restrict__ q, const float* __restrict__ k,
                   const float* __restrict__ v, const int* __restrict__ mask,
                   float* __restrict__ ctx)
{
    __shared__ float Ks[64 * KST];
    __shared__ float Vs[64 * 64];
    __shared__ int   msk[64];

    int tid = threadIdx.x;
    int w = tid >> 5, lane = tid & 31;
    int lq = lane >> 2, lr = lane & 3;
    int bh = blockIdx.y;
    int b = bh >> 4, h = bh & 15;
    int q0 = blockIdx.x * 128;

    const float* qg = q + ((long)(b * SS + q0 + w * 16)) * DD + h * DKK;
    const float* kg = k + ((long)b * SS) * DD + h * DKK;
    const float* vg = v + ((long)b * SS) * DD + h * DKK;
    const int* mrow = mask + b * SS;

    float qa[8][4];
    #pragma unroll
    for (int ks = 0; ks < 8; ks++) {
        qa[ks][0] = qg[(long)lq * DD + ks * 8 + lr];
        qa[ks][1] = qg[(long)(lq + 8) * DD + ks * 8 + lr];
        qa[ks][2] = qg[(long)lq * DD + ks * 8 + lr + 4];
        qa[ks][3] = qg[(long)(lq + 8) * DD + ks * 8 + lr + 4];
    }

    float m0 = -INFINITY, m1 = -INFINITY, l0 = 0.f, l1 = 0.f;
    float oacc[8][4];
    #pragma unroll
    for (int nt = 0; nt < 8; nt++)
        #pragma unroll
        for (int e = 0; e < 4; e++) oacc[nt][e] = 0.f;

    for (int kt = 0; kt < 16; kt++) {
        int k0 = kt * 64;
        __syncthreads();
        #pragma unroll
        for (int i = 0; i < 4; i++) {
            int fi = tid + i * 256;
            int kr = fi >> 4;
            int c4 = (fi & 15) << 2;
            float4 tk = *(const float4*)(kg + (long)(k0 + kr) * DD + c4);
            *(float4*)&Ks[kr * KST + c4] = tk;
            float4 tv = *(const float4*)(vg + (long)(k0 + kr) * DD + c4);
            *(float4*)&Vs[kr * 64 + (c4 ^ ((kr & 3) << 3))] = tv;
        }
        if (tid < 16) ((int4*)msk)[tid] = ((const int4*)(mrow + k0))[tid];
        __syncthreads();

        float sacc[8][4];
        #pragma unroll
        for (int nt = 0; nt < 8; nt++)
            #pragma unroll
            for (int e = 0; e < 4; e++) sacc[nt][e] = 0.f;

        #pragma unroll
        for (int nt = 0; nt < 8; nt++) {
            int rb = (nt * 8 + lq) * KST;
            #pragma unroll
            for (int ks = 0; ks < 8; ks++) {
                float b0 = Ks[rb + ks * 8 + lr];
                float b1 = Ks[rb + ks * 8 + lr + 4];
                mma_tf32(sacc[nt], qa[ks], b0, b1);
            }
        }

        float rmax0 = -INFINITY, rmax1 = -INFINITY;
        #pragma unroll
        for (int nt = 0; nt < 8; nt++) {
            int c = nt * 8 + lr * 2;
            int mk0 = msk[c], mk1 = msk[c + 1];
            float s0 = sacc[nt][0] * 0.125f; if (mk0 == 0) s0 = -1e9f;
            float s1 = sacc[nt][1] * 0.125f; if (mk1 == 0) s1 = -1e9f;
            float s2 = sacc[nt][2] * 0.125f; if (mk0 == 0) s2 = -1e9f;
            float s3 = sacc[nt][3] * 0.125f; if (mk1 == 0) s3 = -1e9f;
            sacc[nt][0] = s0; sacc[nt][1] = s1; sacc[nt][2] = s2; sacc[nt][3] = s3;
            rmax0 = fmaxf(rmax0, fmaxf(s0, s1));
            rmax1 = fmaxf(rmax1, fmaxf(s2, s3));
        }
        rmax0 = fmaxf(rmax0, __shfl_xor_sync(0xffffffffu, rmax0, 1));
        rmax0 = fmaxf(rmax0, __shfl_xor_sync(0xffffffffu, rmax0, 2));
        rmax1 = fmaxf(rmax1, __shfl_xor_sync(0xffffffffu, rmax1, 1));
        rmax1 = fmaxf(rmax1, __shfl_xor_sync(0xffffffffu, rmax1, 2));
        float mn0 = fmaxf(m0, rmax0), mn1 = fmaxf(m1, rmax1);
        float corr0 = __expf(m0 - mn0), corr1 = __expf(m1 - mn1);
        float ps0 = 0.f, ps1 = 0.f;
        #pragma unroll
        for (int nt = 0; nt < 8; nt++) {
            float p0 = __expf(sacc[nt][0] - mn0);
            float p1 = __expf(sacc[nt][1] - mn0);
            float p2 = __expf(sacc[nt][2] - mn1);
            float p3 = __expf(sacc[nt][3] - mn1);
            ps0 += p0 + p1; ps1 += p2 + p3;
            sacc[nt][0] = p0; sacc[nt][1] = p1; sacc[nt][2] = p2; sacc[nt][3] = p3;
        }
        ps0 += __shfl_xor_sync(0xffffffffu, ps0, 1);
        ps0 += __shfl_xor_sync(0xffffffffu, ps0, 2);
        ps1 += __shfl_xor_sync(0xffffffffu, ps1, 1);
        ps1 += __shfl_xor_sync(0xffffffffu, ps1, 2);
        l0 = l0 * corr0 + ps0; m0 = mn0;
        l1 = l1 * corr1 + ps1; m1 = mn1;
        #pragma unroll
        for (int nt = 0; nt < 8; nt++) {
            oacc[nt][0] *= corr0; oacc[nt][1] *= corr0;
            oacc[nt][2] *= corr1; oacc[nt][3] *= corr1;
        }

        int base = lane & ~3;
        int src0 = base | (lr >> 1);
        int src1 = src0 | 2;
        int sel = lr & 1;
        #pragma unroll
        for (int ks = 0; ks < 8; ks++) {
            float v0 = __shfl_sync(0xffffffffu, sacc[ks][0], src0);
            float v1 = __shfl_sync(0xffffffffu, sacc[ks][1], src0);
            float v2 = __shfl_sync(0xffffffffu, sacc[ks][2], src0);
            float v3 = __shfl_sync(0xffffffffu, sacc[ks][3], src0);
            float w0 = __shfl_sync(0xffffffffu, sacc[ks][0], src1);
            float w1 = __shfl_sync(0xffffffffu, sacc[ks][1], src1);
            float w2 = __shfl_sync(0xffffffffu, sacc[ks][2], src1);
            float w3 = __shfl_sync(0xffffffffu, sacc[ks][3], src1);
            float pa[4];
            pa[0] = tf32r(sel ? v1 : v0);
            pa[1] = tf32r(sel ? v3 : v2);
            pa[2] = tf32r(sel ? w1 : w0);
            pa[3] = tf32r(sel ? w3 : w2);
            int r0 = (ks * 8 + lr) * 64;
            int r1 = (ks * 8 + lr + 4) * 64;
            int xo = lr << 3;
            #pragma unroll
            for (int nt = 0; nt < 8; nt++) {
                int sw = (nt * 8 + lq) ^ xo;
                float b0 = Vs[r0 + sw];
                float b1 = Vs[r1 + sw];
                mma_tf32(oacc[nt], pa, b0, b1);
            }
        }
    }

    float inv0 = 1.f / l0, inv1 = 1.f / l1;
    long row0 = (long)(b * SS + q0 + w * 16 + lq) * DD + h * DKK;
    long row1 = row0 + 8 * DD;
    #pragma unroll
    for (int nt = 0; nt < 8; nt++) {
        int c = nt * 8 + lr * 2;
        float2 o0, o1;
        o0.x = tf32r(oacc[nt][0] * inv0); o0.y = tf32r(oacc[nt][1] * inv0);
        o1.x = tf32r(oacc[nt][2] * inv1); o1.y = tf32r(oacc[nt][3] * inv1);
        *(float2*)(ctx + row0 + c) = o0;
        *(float2*)(ctx + row1 + c) = o1;
    }
}

extern "C" void kernel_launch(void* const* d_in, const int* in_sizes, int n_in,
                              void* d_out, int out_size)
{
    const float* x    = (const float*)d_in[0];
    const int*   mask = (const int*)  d_in[1];
    const float* wq = (const float*)d_in[2];  const float* bq = (const float*)d_in[3];
    const float* wk = (const float*)d_in[4];  const float* bk = (const float*)d_in[5];
    const float* wv = (const float*)d_in[6];  const float* bv = (const float*)d_in[7];
    const float* wo = (const float*)d_in[8];  const float* bo = (const float*)d_in[9];
    const float* w1 = (const float*)d_in[10]; const float* b1 = (const float*)d_in[11];
    const float* w2 = (const float*)d_in[12]; const float* b2 = (const float*)d_in[13];
    const float* a1 = (const float*)d_in[14]; const float* be1 = (const float*)d_in[15];
    const float* a2 = (const float*)d_in[16]; const float* be2 = (const float*)d_in[17];
    float* out = (float*)d_out;

    float *xn, *q, *k, *v, *ctx, *x1, *xn2, *ffh;
    float *wqr, *wkr, *wvr, *wor, *w1r, *w2r;
    cudaGetSymbolAddress((void**)&xn,  g_xn);
    cudaGetSymbolAddress((void**)&q,   g_q);
    cudaGetSymbolAddress((void**)&k,   g_k);
    cudaGetSymbolAddress((void**)&v,   g_v);
    cudaGetSymbolAddress((void**)&ctx, g_ctx);
    cudaGetSymbolAddress((void**)&x1,  g_x1);
    cudaGetSymbolAddress((void**)&xn2, g_xn2);
    cudaGetSymbolAddress((void**)&ffh, g_ffh);
    cudaGetSymbolAddress((void**)&wqr, g_wq);
    cudaGetSymbolAddress((void**)&wkr, g_wk);
    cudaGetSymbolAddress((void**)&wvr, g_wv);
    cudaGetSymbolAddress((void**)&wor, g_wo);
    cudaGetSymbolAddress((void**)&w1r, g_w1);
    cudaGetSymbolAddress((void**)&w2r, g_w2);

    int nDD4 = DD * DD / 4;
    int nDF4 = DD * DFFV / 4;
    tf32_round_kernel<<<nDD4 / 256, 256>>>(wq, wqr, nDD4);
    tf32_round_kernel<<<nDD4 / 256, 256>>>(wk, wkr, nDD4);
    tf32_round_kernel<<<nDD4 / 256, 256>>>(wv, wvr, nDD4);
    tf32_round_kernel<<<nDD4 / 256, 256>>>(wo, wor, nDD4);
    tf32_round_kernel<<<nDF4 / 256, 256>>>(w1, w1r, nDF4);
    tf32_round_kernel<<<nDF4 / 256, 256>>>(w2, w2r, nDF4);

    dim3 gD (DD   / 128, MR / 128);
    dim3 gFF(DFFV / 128, MR / 128);

    layernorm_kernel<<<MR, 256>>>(x, xn, a1, be1);
    mma_gemm<true,  false, false, true ><<<gD, 128>>>(xn, wqr, bq, nullptr, q, DD, DD);
    mma_gemm<true,  false, false, true ><<<gD, 128>>>(xn, wkr, bk, nullptr, k, DD, DD);
    mma_gemm<true,  false, false, true ><<<gD, 128>>>(xn, wvr, bv, nullptr, v, DD, DD);
    attention_mma<<<dim3(SS / 128, BB * HH), 256>>>(q, k, v, mask, ctx);
    mma_gemm<true,  false, true,  false><<<gD, 128>>>(ctx, wor, bo, x, x1, DD, DD);
    layernorm_kernel<<<MR, 256>>>(x1, xn2, a2, be2);
    mma_gemm<true,  true,  false, true ><<<gFF, 128>>>(xn2, w1r, b1, nullptr, ffh, DD, DFFV);
    mma_gemm<true,  false, true,  false><<<gD, 128>>>(ffh, w2r, b2, x1, out, DFFV, DD);
}

// round 10
// speedup vs baseline: 2.1846x; 1.7742x over previous
#include <cuda_runtime.h>
#include <math.h>
#include <stdint.h>

#define BB 4
#define SS 1024
#define DD 1024
#define HH 16
#define DKK 64
#define DFFV 4096
#define MR (BB*SS)
#define LDQKV 3072
#define LN_EPS 1e-6f

__device__ float g_xn  [MR*DD];
__device__ float g_qkv [MR*LDQKV];
__device__ float g_ctx [MR*DD];
__device__ float g_x1  [MR*DD];
__device__ float g_xn2 [MR*DD];
__device__ float g_ffh [MR*DFFV];
__device__ float g_wqkv[LDQKV*DD];   // [3072][1024] transposed tf32
__device__ float g_wo  [DD*DD];      // [N][K]
__device__ float g_w1t [DFFV*DD];    // [4096][1024]
__device__ float g_w2t [DD*DFFV];    // [1024][4096]
__device__ float g_bqkv[LDQKV];

__device__ __forceinline__ float tf32r(float x) {
    unsigned u;
    asm("cvt.rna.tf32.f32 %0, %1;" : "=r"(u) : "f"(x));
    return __uint_as_float(u);
}
__device__ __forceinline__ void mma_tf32(float* c, const float* a, float b0f, float b1f) {
    asm volatile(
        "mma.sync.aligned.m16n8k8.row.col.f32.tf32.tf32.f32 "
        "{%0,%1,%2,%3}, {%4,%5,%6,%7}, {%8,%9}, {%0,%1,%2,%3};\n"
        : "+f"(c[0]), "+f"(c[1]), "+f"(c[2]), "+f"(c[3])
        : "r"(__float_as_uint(a[0])), "r"(__float_as_uint(a[1])),
          "r"(__float_as_uint(a[2])), "r"(__float_as_uint(a[3])),
          "r"(__float_as_uint(b0f)), "r"(__float_as_uint(b1f)));
}
__device__ __forceinline__ void cpasync16(uint32_t saddr, const float* g) {
    asm volatile("cp.async.cg.shared.global [%0], [%1], 16;\n" :: "r"(saddr), "l"(g));
}
__device__ __forceinline__ void cpasync_commit() {
    asm volatile("cp.async.commit_group;\n" ::: "memory");
}
__device__ __forceinline__ void cpasync_wait0() {
    asm volatile("cp.async.wait_group 0;\n" ::: "memory");
}
__device__ __forceinline__ uint32_t cvta_s(const void* p) {
    return (uint32_t)__cvta_generic_to_shared(p);
}
#define SWZ128(o) ((o) ^ (((o) >> 3) & 0x70))

// -------- weight transpose + tf32 round: out[n][k] = tf32(in[k][n]) --------
__global__ __launch_bounds__(256)
void transpose_tf32(const float* __restrict__ in, float* __restrict__ out, int Kd, int Nd)
{
    __shared__ float tile[32][33];
    int bx = blockIdx.x * 32, by = blockIdx.y * 32;
    int x = threadIdx.x, y = threadIdx.y;
    #pragma unroll
    for (int i = 0; i < 32; i += 8)
        tile[y + i][x] = in[(long)(by + y + i) * Nd + bx + x];
    __syncthreads();
    #pragma unroll
    for (int i = 0; i < 32; i += 8)
        out[(long)(bx + y + i) * Kd + by + x] = tf32r(tile[x][y + i]);
}

__global__ void biascat_kernel(const float* bq, const float* bk, const float* bv, float* o)
{
    int i = blockIdx.x * 256 + threadIdx.x;
    if (i < DD)            o[i] = bq[i];
    else if (i < 2 * DD)   o[i] = bk[i - DD];
    else if (i < 3 * DD)   o[i] = bv[i - 2 * DD];
}

// LayerNorm: torch ddof=1, eps on std; output tf32-rounded
__global__ __launch_bounds__(256)
void layernorm_kernel(const float* __restrict__ x, float* __restrict__ out,
                      const float* __restrict__ alpha, const float* __restrict__ beta)
{
    int row = blockIdx.x;
    float4 v = ((const float4*)(x + (long)row * DD))[threadIdx.x];
    float s  = v.x + v.y + v.z + v.w;
    float sq = v.x*v.x + v.y*v.y + v.z*v.z + v.w*v.w;
    #pragma unroll
    for (int o = 16; o; o >>= 1) {
        s  += __shfl_down_sync(0xffffffffu, s,  o);
        sq += __shfl_down_sync(0xffffffffu, sq, o);
    }
    __shared__ float red[16];
    __shared__ float stats[2];
    int warp = threadIdx.x >> 5, lane = threadIdx.x & 31;
    if (lane == 0) { red[warp] = s; red[warp + 8] = sq; }
    __syncthreads();
    if (threadIdx.x == 0) {
        float ts = 0.f, tq = 0.f;
        #pragma unroll
        for (int i = 0; i < 8; i++) { ts += red[i]; tq += red[i + 8]; }
        float mean = ts / (float)DD;
        float var  = (tq - (float)DD * mean * mean) / (float)(DD - 1);
        var = fmaxf(var, 0.f);
        stats[0] = mean; stats[1] = 1.f / (sqrtf(var) + LN_EPS);
    }
    __syncthreads();
    float mean = stats[0], rstd = stats[1];
    float a = alpha[0], b = beta[0];
    float4 o;
    o.x = tf32r(a * (v.x - mean) * rstd + b);
    o.y = tf32r(a * (v.y - mean) * rstd + b);
    o.z = tf32r(a * (v.z - mean) * rstd + b);
    o.w = tf32r(a * (v.w - mean) * rstd + b);
    ((float4*)(out + (long)row * DD))[threadIdx.x] = o;
}

// ------------- tf32 GEMM: C[M,N] = A[M,K] @ Bt[N,K]^T -----------------------
// CTA 128x128, 4 warps (2x2) of 64x64, BK=32 (one SW128 128B row per chunk),
// 2-stage cp.async double buffer in XOR-swizzled smem.
#define G_STAGE 32768
#define G_DYN (2 * G_STAGE)

template<bool BIAS, bool RELU, bool RES, bool CVT>
__global__ void __launch_bounds__(128, 2)
mma_gemm32(const float* __restrict__ A, const float* __restrict__ Bt,
           const float* __restrict__ bias, const float* __restrict__ res,
           float* __restrict__ C, int K, int N)
{
    extern __shared__ __align__(1024) char smp[];

    int tid = threadIdx.x, warp = tid >> 5, lane = tid & 31;
    int lq = lane >> 2, lr = lane & 3;
    int wm = warp >> 1, wn = warp & 1;
    int rowBase = blockIdx.y << 7, colBase = blockIdx.x << 7;

    // loader: thread covers rows rg+16g (g=0..7), 16B segment seg
    int rg = tid >> 3, seg = tid & 7;
    const float* Ag = A  + (long)rowBase * K + seg * 4;
    const float* Bg = Bt + (long)colBase * K + seg * 4;
    uint32_t swo = SWZ128((uint32_t)(rg * 128 + seg * 16));
    uint32_t sb = cvta_s(smp);

    float acc[4][8][4];
    #pragma unroll
    for (int i = 0; i < 4; i++)
        #pragma unroll
        for (int j = 0; j < 8; j++)
            #pragma unroll
            for (int e = 0; e < 4; e++) acc[i][j][e] = 0.f;

    int T = K >> 5;
    // prologue: stage 0
    #pragma unroll
    for (int g = 0; g < 8; g++) {
        int r = rg + g * 16;
        uint32_t o = swo + g * 2048;
        cpasync16(sb + o,         Ag + (long)r * K);
        cpasync16(sb + 16384 + o, Bg + (long)r * K);
    }
    cpasync_commit();

    uint32_t xorc = (uint32_t)lq << 4;   // swizzle XOR for frag reads

    for (int t = 0; t < T; t++) {
        cpasync_wait0();
        __syncthreads();
        int buf = t & 1;
        if (t + 1 < T) {
            long k0 = (long)(t + 1) * 32;
            uint32_t ab = sb + (buf ^ 1) * G_STAGE;
            #pragma unroll
            for (int g = 0; g < 8; g++) {
                int r = rg + g * 16;
                uint32_t o = swo + g * 2048;
                cpasync16(ab + o,         Ag + (long)r * K + k0);
                cpasync16(ab + 16384 + o, Bg + (long)r * K + k0);
            }
            cpasync_commit();
        }
        const char* Ab = smp + buf * G_STAGE;
        const char* Bb = Ab + 16384;

        #pragma unroll
        for (int ks = 0; ks < 4; ks++) {
            uint32_t c0 = ((uint32_t)(ks * 8 + lr) * 4) ^ xorc;
            uint32_t c1 = ((uint32_t)(ks * 8 + lr + 4) * 4) ^ xorc;
            float a[4][4];
            #pragma unroll
            for (int mt = 0; mt < 4; mt++) {
                const char* rp = Ab + (wm * 64 + mt * 16 + lq) * 128;
                a[mt][0] = *(const float*)(rp + c0);
                a[mt][1] = *(const float*)(rp + 1024 + c0);
                a[mt][2] = *(const float*)(rp + c1);
                a[mt][3] = *(const float*)(rp + 1024 + c1);
            }
            float b[8][2];
            #pragma unroll
            for (int nt = 0; nt < 8; nt++) {
                const char* np = Bb + (wn * 64 + nt * 8 + lq) * 128;
                b[nt][0] = *(const float*)(np + c0);
                b[nt][1] = *(const float*)(np + c1);
            }
            #pragma unroll
            for (int mt = 0; mt < 4; mt++)
                #pragma unroll
                for (int nt = 0; nt < 8; nt++)
                    mma_tf32(acc[mt][nt], a[mt], b[nt][0], b[nt][1]);
        }
    }

    int erow = rowBase + wm * 64 + lq;
    int ecol = colBase + wn * 64 + lr * 2;
    #pragma unroll
    for (int mt = 0; mt < 4; mt++) {
        #pragma unroll
        for (int nt = 0; nt < 8; nt++) {
            int r = erow + mt * 16;
            int c = ecol + nt * 8;
            float lo0 = acc[mt][nt][0], lo1 = acc[mt][nt][1];
            float hi0 = acc[mt][nt][2], hi1 = acc[mt][nt][3];
            if (BIAS) {
                float2 bv = *(const float2*)(bias + c);
                lo0 += bv.x; lo1 += bv.y; hi0 += bv.x; hi1 += bv.y;
            }
            if (RELU) {
                lo0 = fmaxf(lo0, 0.f); lo1 = fmaxf(lo1, 0.f);
                hi0 = fmaxf(hi0, 0.f); hi1 = fmaxf(hi1, 0.f);
            }
            if (RES) {
                float2 r0 = *(const float2*)(res + (long)r * N + c);
                float2 r1 = *(const float2*)(res + (long)(r + 8) * N + c);
                lo0 += r0.x; lo1 += r0.y; hi0 += r1.x; hi1 += r1.y;
            }
            if (CVT) {
                lo0 = tf32r(lo0); lo1 = tf32r(lo1);
                hi0 = tf32r(hi0); hi1 = tf32r(hi1);
            }
            float2 wlo = {lo0, lo1}, whi = {hi0, hi1};
            *(float2*)(C + (long)r * N + c)       = wlo;
            *(float2*)(C + (long)(r + 8) * N + c) = whi;
        }
    }
}

// ---------------- tensor-core flash attention (qkv fused buffer) ------------
#define KST 68

__global__ __launch_bounds__(256)
void attention_mma(const float* __restrict__ qkv, const int* __restrict__ mask,
                   float* __restrict__ ctx)
{
    __shared__ float Ks[64 * KST];
    __shared__ float Vs[64 * 64];
    __shared__ int   msk[64];

    int tid = threadIdx.x;
    int w = tid >> 5, lane = tid & 31;
    int lq = lane >> 2, lr = lane & 3;
    int bh = blockIdx.y;
    int b = bh >> 4, h = bh & 15;
    int q0 = blockIdx.x * 128;

    const float* qg = qkv + (long)(b * SS + q0 + w * 16) * LDQKV + h * DKK;
    const float* kg = qkv + (long)(b * SS) * LDQKV + DD + h * DKK;
    const float* vg = qkv + (long)(b * SS) * LDQKV + 2 * DD + h * DKK;
    const int* mrow = mask + b * SS;

    float qa[8][4];
    #pragma unroll
    for (int ks = 0; ks < 8; ks++) {
        qa[ks][0] = qg[(long)lq * LDQKV + ks * 8 + lr];
        qa[ks][1] = qg[(long)(lq + 8) * LDQKV + ks * 8 + lr];
        qa[ks][2] = qg[(long)lq * LDQKV + ks * 8 + lr + 4];
        qa[ks][3] = qg[(long)(lq + 8) * LDQKV + ks * 8 + lr + 4];
    }

    float m0 = -INFINITY, m1 = -INFINITY, l0 = 0.f, l1 = 0.f;
    float oacc[8][4];
    #pragma unroll
    for (int nt = 0; nt < 8; nt++)
        #pragma unroll
        for (int e = 0; e < 4; e++) oacc[nt][e] = 0.f;

    for (int kt = 0; kt < 16; kt++) {
        int k0 = kt * 64;
        __syncthreads();
        #pragma unroll
        for (int i = 0; i < 4; i++) {
            int fi = tid + i * 256;
            int kr = fi >> 4;
            int c4 = (fi & 15) << 2;
            float4 tk = *(const float4*)(kg + (long)(k0 + kr) * LDQKV + c4);
            *(float4*)&Ks[kr * KST + c4] = tk;
            float4 tv = *(const float4*)(vg + (long)(k0 + kr) * LDQKV + c4);
            *(float4*)&Vs[kr * 64 + (c4 ^ ((kr & 3) << 3))] = tv;
        }
        if (tid < 16) ((int4*)msk)[tid] = ((const int4*)(mrow + k0))[tid];
        __syncthreads();

        float sacc[8][4];
        #pragma unroll
        for (int nt = 0; nt < 8; nt++)
            #pragma unroll
            for (int e = 0; e < 4; e++) sacc[nt][e] = 0.f;

        #pragma unroll
        for (int nt = 0; nt < 8; nt++) {
            int rb = (nt * 8 + lq) * KST;
            #pragma unroll
            for (int ks = 0; ks < 8; ks++) {
                float b0 = Ks[rb + ks * 8 + lr];
                float b1 = Ks[rb + ks * 8 + lr + 4];
                mma_tf32(sacc[nt], qa[ks], b0, b1);
            }
        }

        float rmax0 = -INFINITY, rmax1 = -INFINITY;
        #pragma unroll
        for (int nt = 0; nt < 8; nt++) {
            int c = nt * 8 + lr * 2;
            int mk0 = msk[c], mk1 = msk[c + 1];
            float s0 = sacc[nt][0] * 0.125f; if (mk0 == 0) s0 = -1e9f;
            float s1 = sacc[nt][1] * 0.125f; if (mk1 == 0) s1 = -1e9f;
            float s2 = sacc[nt][2] * 0.125f; if (mk0 == 0) s2 = -1e9f;
            float s3 = sacc[nt][3] * 0.125f; if (mk1 == 0) s3 = -1e9f;
            sacc[nt][0] = s0; sacc[nt][1] = s1; sacc[nt][2] = s2; sacc[nt][3] = s3;
            rmax0 = fmaxf(rmax0, fmaxf(s0, s1));
            rmax1 = fmaxf(rmax1, fmaxf(s2, s3));
        }
        rmax0 = fmaxf(rmax0, __shfl_xor_sync(0xffffffffu, rmax0, 1));
        rmax0 = fmaxf(rmax0, __shfl_xor_sync(0xffffffffu, rmax0, 2));
        rmax1 = fmaxf(rmax1, __shfl_xor_sync(0xffffffffu, rmax1, 1));
        rmax1 = fmaxf(rmax1, __shfl_xor_sync(0xffffffffu, rmax1, 2));
        float mn0 = fmaxf(m0, rmax0), mn1 = fmaxf(m1, rmax1);
        float corr0 = __expf(m0 - mn0), corr1 = __expf(m1 - mn1);
        float ps0 = 0.f, ps1 = 0.f;
        #pragma unroll
        for (int nt = 0; nt < 8; nt++) {
            float p0 = __expf(sacc[nt][0] - mn0);
            float p1 = __expf(sacc[nt][1] - mn0);
            float p2 = __expf(sacc[nt][2] - mn1);
            float p3 = __expf(sacc[nt][3] - mn1);
            ps0 += p0 + p1; ps1 += p2 + p3;
            sacc[nt][0] = p0; sacc[nt][1] = p1; sacc[nt][2] = p2; sacc[nt][3] = p3;
        }
        ps0 += __shfl_xor_sync(0xffffffffu, ps0, 1);
        ps0 += __shfl_xor_sync(0xffffffffu, ps0, 2);
        ps1 += __shfl_xor_sync(0xffffffffu, ps1, 1);
        ps1 += __shfl_xor_sync(0xffffffffu, ps1, 2);
        l0 = l0 * corr0 + ps0; m0 = mn0;
        l1 = l1 * corr1 + ps1; m1 = mn1;
        #pragma unroll
        for (int nt = 0; nt < 8; nt++) {
            oacc[nt][0] *= corr0; oacc[nt][1] *= corr0;
            oacc[nt][2] *= corr1; oacc[nt][3] *= corr1;
        }

        int base = lane & ~3;
        int src0 = base | (lr >> 1);
        int src1 = src0 | 2;
        int sel = lr & 1;
        #pragma unroll
        for (int ks = 0; ks < 8; ks++) {
            float v0 = __shfl_sync(0xffffffffu, sacc[ks][0], src0);
            float v1 = __shfl_sync(0xffffffffu, sacc[ks][1], src0);
            float v2 = __shfl_sync(0xffffffffu, sacc[ks][2], src0);
            float v3 = __shfl_sync(0xffffffffu, sacc[ks][3], src0);
            float w0 = __shfl_sync(0xffffffffu, sacc[ks][0], src1);
            float w1 = __shfl_sync(0xffffffffu, sacc[ks][1], src1);
            float w2 = __shfl_sync(0xffffffffu, sacc[ks][2], src1);
            float w3 = __shfl_sync(0xffffffffu, sacc[ks][3], src1);
            float pa[4];
            pa[0] = tf32r(sel ? v1 : v0);
            pa[1] = tf32r(sel ? v3 : v2);
            pa[2] = tf32r(sel ? w1 : w0);
            pa[3] = tf32r(sel ? w3 : w2);
            int r0 = (ks * 8 + lr) * 64;
            int r1 = (ks * 8 + lr + 4) * 64;
            int xo = lr << 3;
            #pragma unroll
            for (int nt = 0; nt < 8; nt++) {
                int sw = (nt * 8 + lq) ^ xo;
                float b0 = Vs[r0 + sw];
                float b1 = Vs[r1 + sw];
                mma_tf32(oacc[nt], pa, b0, b1);
            }
        }
    }

    float inv0 = 1.f / l0, inv1 = 1.f / l1;
    long row0 = (long)(b * SS + q0 + w * 16 + lq) * DD + h * DKK;
    long row1 = row0 + 8 * DD;
    #pragma unroll
    for (int nt = 0; nt < 8; nt++) {
        int c = nt * 8 + lr * 2;
        float2 o0, o1;
        o0.x = tf32r(oacc[nt][0] * inv0); o0.y = tf32r(oacc[nt][1] * inv0);
        o1.x = tf32r(oacc[nt][2] * inv1); o1.y = tf32r(oacc[nt][3] * inv1);
        *(float2*)(ctx + row0 + c) = o0;
        *(float2*)(ctx + row1 + c) = o1;
    }
}

extern "C" void kernel_launch(void* const* d_in, const int* in_sizes, int n_in,
                              void* d_out, int out_size)
{
    const float* x    = (const float*)d_in[0];
    const int*   mask = (const int*)  d_in[1];
    const float* wq = (const float*)d_in[2];  const float* bq = (const float*)d_in[3];
    const float* wk = (const float*)d_in[4];  const float* bk = (const float*)d_in[5];
    const float* wv = (const float*)d_in[6];  const float* bv = (const float*)d_in[7];
    const float* wo = (const float*)d_in[8];  const float* bo = (const float*)d_in[9];
    const float* w1 = (const float*)d_in[10]; const float* b1 = (const float*)d_in[11];
    const float* w2 = (const float*)d_in[12]; const float* b2 = (const float*)d_in[13];
    const float* a1 = (const float*)d_in[14]; const float* be1 = (const float*)d_in[15];
    const float* a2 = (const float*)d_in[16]; const float* be2 = (const float*)d_in[17];
    float* out = (float*)d_out;

    float *xn, *qkv, *ctx, *x1, *xn2, *ffh;
    float *wqkvt, *wot, *w1t, *w2t, *bqkv;
    cudaGetSymbolAddress((void**)&xn,    g_xn);
    cudaGetSymbolAddress((void**)&qkv,   g_qkv);
    cudaGetSymbolAddress((void**)&ctx,   g_ctx);
    cudaGetSymbolAddress((void**)&x1,    g_x1);
    cudaGetSymbolAddress((void**)&xn2,   g_xn2);
    cudaGetSymbolAddress((void**)&ffh,   g_ffh);
    cudaGetSymbolAddress((void**)&wqkvt, g_wqkv);
    cudaGetSymbolAddress((void**)&wot,   g_wo);
    cudaGetSymbolAddress((void**)&w1t,   g_w1t);
    cudaGetSymbolAddress((void**)&w2t,   g_w2t);
    cudaGetSymbolAddress((void**)&bqkv,  g_bqkv);

    cudaFuncSetAttribute(mma_gemm32<true,false,false,true >, cudaFuncAttributeMaxDynamicSharedMemorySize, G_DYN);
    cudaFuncSetAttribute(mma_gemm32<true,false,true ,false>, cudaFuncAttributeMaxDynamicSharedMemorySize, G_DYN);
    cudaFuncSetAttribute(mma_gemm32<true,true ,false,true >, cudaFuncAttributeMaxDynamicSharedMemorySize, G_DYN);

    // weight prep: transpose to [N][K] + tf32 round
    transpose_tf32<<<dim3(32, 32),  dim3(32, 8)>>>(wq, wqkvt,               DD, DD);
    transpose_tf32<<<dim3(32, 32),  dim3(32, 8)>>>(wk, wqkvt + DD * DD,     DD, DD);
    transpose_tf32<<<dim3(32, 32),  dim3(32, 8)>>>(wv, wqkvt + 2 * DD * DD, DD, DD);
    transpose_tf32<<<dim3(32, 32),  dim3(32, 8)>>>(wo, wot, DD, DD);
    transpose_tf32<<<dim3(128, 32), dim3(32, 8)>>>(w1, w1t, DD, DFFV);
    transpose_tf32<<<dim3(32, 128), dim3(32, 8)>>>(w2, w2t, DFFV, DD);
    biascat_kernel<<<LDQKV / 256, 256>>>(bq, bk, bv, bqkv);

    dim3 gQKV(LDQKV / 128, MR / 128);  // (24, 32)
    dim3 gD  (DD    / 128, MR / 128);  // (8, 32)
    dim3 gFF (DFFV  / 128, MR / 128);  // (32, 32)

    layernorm_kernel<<<MR, 256>>>(x, xn, a1, be1);
    mma_gemm32<true,false,false,true ><<<gQKV, 128, G_DYN>>>(xn, wqkvt, bqkv, nullptr, qkv, DD, LDQKV);
    attention_mma<<<dim3(SS / 128, BB * HH), 256>>>(qkv, mask, ctx);
    mma_gemm32<true,false,true ,false><<<gD, 128, G_DYN>>>(ctx, wot, bo, x, x1, DD, DD);
    layernorm_kernel<<<MR, 256>>>(x1, xn2, a2, be2);
    mma_gemm32<true,true ,false,true ><<<gFF, 128, G_DYN>>>(xn2, w1t, b1, nullptr, ffh, DD, DFFV);
    mma_gemm32<true,false,true ,false><<<gD, 128, G_DYN>>>(ffh, w2t, b2, x1, out, DFFV, DD);
}